// round 3
// baseline (speedup 1.0000x reference)
#include <cuda_runtime.h>

// Problem: B=1, H=W=D=128.
// dti: (6,128,128,128) f32 ; ddf: (3,128,128,128) f32 ; out: (6,128,128,128) f32
#define NV (128*128*128)
#define NTOT (6*NV)

// 48MB scratch: dti shifted by one element (dti_shift[k] = dti[k+1])
__device__ float g_dti_shift[NTOT];

__device__ __forceinline__ float frcp_a(float x)  { float r; asm("rcp.approx.f32 %0, %1;"   : "=f"(r) : "f"(x)); return r; }
__device__ __forceinline__ float fsqrt_a(float x) { float r; asm("sqrt.approx.f32 %0, %1;"  : "=f"(r) : "f"(x)); return r; }
__device__ __forceinline__ float frsqrt_a(float x){ float r; asm("rsqrt.approx.f32 %0, %1;" : "=f"(r) : "f"(x)); return r; }

// ---------------- shift-copy pre-pass: g_dti_shift[k] = dti[k+1] ------------
__global__ __launch_bounds__(256)
void shift_copy_kernel(const float4* __restrict__ src)
{
    const int j = blockIdx.x * 256 + threadIdx.x;       // [0, NTOT/4)
    const int total = NTOT / 4;
    float4 a = src[j];
    float bx = 0.0f;
    if (j + 1 < total) bx = ((const float*)src)[4 * j + 4];
    float4 o;
    o.x = a.y; o.y = a.z; o.z = a.w; o.w = bx;
    ((float4*)g_dti_shift)[j] = o;
}

__global__ __launch_bounds__(256)
void warp_dti_kernel(const float* __restrict__ dti,
                     const float* __restrict__ ddf,
                     float* __restrict__ out)
{
    const int v = blockIdx.x * 256 + threadIdx.x;   // grid exactly covers NV
    const int z = v & 127;
    const int y = (v >> 7) & 127;
    const int x = v >> 14;

    // ---------------- displacement at this voxel ----------------
    const float dx = ddf[v];
    const float dy = ddf[NV + v];
    const float dz = ddf[2 * NV + v];

    // ---------------- trilinear warp coords (border clamp) ----------------
    float cx = fminf(fmaxf((float)x + dx, 0.0f), 127.0f);
    float cy = fminf(fmaxf((float)y + dy, 0.0f), 127.0f);
    float cz = fminf(fmaxf((float)z + dz, 0.0f), 127.0f);

    float x0f = floorf(cx), y0f = floorf(cy), z0f = floorf(cz);
    float fx = cx - x0f, fy = cy - y0f, fz = cz - z0f;
    int x0 = (int)x0f, y0 = (int)y0f, z0 = (int)z0f;
    int x1 = min(x0 + 1, 127), y1 = min(y0 + 1, 127);

    const int pbase = (x0 << 14) | (y0 << 7) | z0;
    const int ddy = (y1 - y0) << 7;
    const int ddx = (x1 - x0) << 14;

    // Aligned float2 source for the z-pair (z0, z0+1):
    //   z0 even: float2 at dti + i          (8B aligned)
    //   z0 odd : float2 at g_dti_shift+(i-1) (8B aligned), = (dti[i], dti[i+1])
    // z0==127 only occurs with fz==0, so the .y lane is weighted by zero.
    const char* gb = (z0 & 1) ? ((const char*)g_dti_shift - 4) : (const char*)dti;

    const float gx0 = 1.0f - fx, gy0 = 1.0f - fy;
    const float w00 = gx0 * gy0;
    const float w01 = gx0 * fy;
    const float w10 = fx  * gy0;
    const float w11 = fx  * fy;

    float m[6];
    #pragma unroll
    for (int c = 0; c < 6; c++) {
        const char* pc = gb + 4 * (size_t)(c * NV + pbase);
        float2 v00 = *(const float2*)(pc);
        float2 v01 = *(const float2*)(pc + 4 * ddy);
        float2 v10 = *(const float2*)(pc + 4 * ddx);
        float2 v11 = *(const float2*)(pc + 4 * (ddx + ddy));
        float l00 = fmaf(fz, v00.y - v00.x, v00.x);
        float l01 = fmaf(fz, v01.y - v01.x, v01.x);
        float l10 = fmaf(fz, v10.y - v10.x, v10.x);
        float l11 = fmaf(fz, v11.y - v11.x, v11.x);
        float a = w00 * l00;
        a = fmaf(w01, l01, a);
        a = fmaf(w10, l10, a);
        a = fmaf(w11, l11, a);
        m[c] = a;
    }

    // ---------------- Jacobian J = I + d(ddf)/dx (jnp.gradient semantics) ----
    const int xp = min(x + 1, 127), xm = max(x - 1, 0);
    const int yp = min(y + 1, 127), ym = max(y - 1, 0);
    const int zp = min(z + 1, 127), zm = max(z - 1, 0);
    const float sx = 1.5f - 0.5f * (float)(xp - xm);
    const float sy = 1.5f - 0.5f * (float)(yp - ym);
    const float sz = 1.5f - 0.5f * (float)(zp - zm);

    const int ixp = (xp << 14) | (y << 7) | z;
    const int ixm = (xm << 14) | (y << 7) | z;
    const int iyp = (x << 14) | (yp << 7) | z;
    const int iym = (x << 14) | (ym << 7) | z;
    const int izp = (x << 14) | (y << 7) | zp;
    const int izm = (x << 14) | (y << 7) | zm;

    float X[3][3];
    #pragma unroll
    for (int i = 0; i < 3; i++) {
        const float* p = ddf + i * NV;
        X[i][0] = (p[ixp] - p[ixm]) * sx;
        X[i][1] = (p[iyp] - p[iym]) * sy;
        X[i][2] = (p[izp] - p[izm]) * sz;
    }
    X[0][0] += 1.0f;
    X[1][1] += 1.0f;
    X[2][2] += 1.0f;

    // ---------------- polar factor via Newton iteration ---------------------
    // X <- 0.5*(mu*X + (1/mu)*X^{-T}); Frobenius-optimal mu for the first 3
    // iterations, then mu=1 for the last 3.
    #pragma unroll
    for (int it = 0; it < 6; it++) {
        float C00 = X[1][1] * X[2][2] - X[1][2] * X[2][1];
        float C01 = X[1][2] * X[2][0] - X[1][0] * X[2][2];
        float C02 = X[1][0] * X[2][1] - X[1][1] * X[2][0];
        float C10 = X[0][2] * X[2][1] - X[0][1] * X[2][2];
        float C11 = X[0][0] * X[2][2] - X[0][2] * X[2][0];
        float C12 = X[0][1] * X[2][0] - X[0][0] * X[2][1];
        float C20 = X[0][1] * X[1][2] - X[0][2] * X[1][1];
        float C21 = X[0][2] * X[1][0] - X[0][0] * X[1][2];
        float C22 = X[0][0] * X[1][1] - X[0][1] * X[1][0];

        float det = X[0][0] * C00 + X[0][1] * C01 + X[0][2] * C02;
        float ad = fabsf(det);
        det = (ad < 1e-30f) ? ((det < 0.0f) ? -1e-30f : 1e-30f) : det;
        float rdet = frcp_a(det);

        float ca, cb;
        if (it < 3) {
            float a2 = X[0][0]*X[0][0] + X[0][1]*X[0][1] + X[0][2]*X[0][2]
                     + X[1][0]*X[1][0] + X[1][1]*X[1][1] + X[1][2]*X[1][2]
                     + X[2][0]*X[2][0] + X[2][1]*X[2][1] + X[2][2]*X[2][2];
            float c2s = C00*C00 + C01*C01 + C02*C02
                      + C10*C10 + C11*C11 + C12*C12
                      + C20*C20 + C21*C21 + C22*C22;
            float r = (c2s * rdet * rdet) * frcp_a(a2);
            float t = fsqrt_a(r);
            float mu  = fsqrt_a(t);
            float imu = frsqrt_a(t);
            ca = 0.5f * mu;
            cb = 0.5f * imu * rdet;
        } else {
            ca = 0.5f;
            cb = 0.5f * rdet;
        }

        X[0][0] = ca * X[0][0] + cb * C00;
        X[0][1] = ca * X[0][1] + cb * C01;
        X[0][2] = ca * X[0][2] + cb * C02;
        X[1][0] = ca * X[1][0] + cb * C10;
        X[1][1] = ca * X[1][1] + cb * C11;
        X[1][2] = ca * X[1][2] + cb * C12;
        X[2][0] = ca * X[2][0] + cb * C20;
        X[2][1] = ca * X[2][1] + cb * C21;
        X[2][2] = ca * X[2][2] + cb * C22;
    }

    // ---------------- Dp = R^T M R, M symmetric from warped channels --------
    float M00 = m[0], M01 = m[1], M02 = m[3];
    float M11 = m[2], M12 = m[4], M22 = m[5];

    float A00 = M00 * X[0][0] + M01 * X[1][0] + M02 * X[2][0];
    float A01 = M00 * X[0][1] + M01 * X[1][1] + M02 * X[2][1];
    float A02 = M00 * X[0][2] + M01 * X[1][2] + M02 * X[2][2];
    float A10 = M01 * X[0][0] + M11 * X[1][0] + M12 * X[2][0];
    float A11 = M01 * X[0][1] + M11 * X[1][1] + M12 * X[2][1];
    float A12 = M01 * X[0][2] + M11 * X[1][2] + M12 * X[2][2];
    float A20 = M02 * X[0][0] + M12 * X[1][0] + M22 * X[2][0];
    float A21 = M02 * X[0][1] + M12 * X[1][1] + M22 * X[2][1];
    float A22 = M02 * X[0][2] + M12 * X[1][2] + M22 * X[2][2];

    float Dp00 = X[0][0] * A00 + X[1][0] * A10 + X[2][0] * A20;
    float Dp10 = X[0][1] * A00 + X[1][1] * A10 + X[2][1] * A20;
    float Dp11 = X[0][1] * A01 + X[1][1] * A11 + X[2][1] * A21;
    float Dp20 = X[0][2] * A00 + X[1][2] * A10 + X[2][2] * A20;
    float Dp21 = X[0][2] * A01 + X[1][2] * A11 + X[2][2] * A21;
    float Dp22 = X[0][2] * A02 + X[1][2] * A12 + X[2][2] * A22;

    out[v]          = Dp00;
    out[NV + v]     = Dp10;
    out[2 * NV + v] = Dp11;
    out[3 * NV + v] = Dp20;
    out[4 * NV + v] = Dp21;
    out[5 * NV + v] = Dp22;
}

extern "C" void kernel_launch(void* const* d_in, const int* in_sizes, int n_in,
                              void* d_out, int out_size)
{
    const float* dti = (const float*)d_in[0];   // 6*128^3
    const float* ddf = (const float*)d_in[1];   // 3*128^3
    float* out = (float*)d_out;                 // 6*128^3
    (void)in_sizes; (void)n_in; (void)out_size;

    shift_copy_kernel<<<NTOT / 4 / 256, 256>>>((const float4*)dti);
    warp_dti_kernel<<<NV / 256, 256>>>(dti, ddf, out);
}